// round 14
// baseline (speedup 1.0000x reference)
#include <cuda_runtime.h>
#include <cuda_bf16.h>
#include <cstdint>

#define BATCH 8
#define TE    256
#define TD    128
#define HE    512
#define HC    16
#define DT    8

#define MROWS (BATCH * TE + BATCH * TD)   // 3072 combined A rows
#define MT_WS (BATCH * TE / 128)          // 16 m-tiles for Ws

// ---------------- scratch ----------------
__device__ float g_Ws[BATCH * TE * HE];                     // enc @ W_a (raw)
__device__ float g_Uh[BATCH * TD * HE];                     // dec @ U_a (raw)
__device__ float g_E [BATCH * TD * TE];                     // raw logits
__device__ __align__(16) __nv_bfloat16 g_Ah[MROWS * HE];
__device__ __align__(16) __nv_bfloat16 g_Al[MROWS * HE];
__device__ __align__(16) __nv_bfloat16 g_Bh[2 * HE * HE];
__device__ __align__(16) __nv_bfloat16 g_Bl[2 * HE * HE];

__device__ __forceinline__ float fast_tanh(float x) {
    float y;
    asm("tanh.approx.f32 %0, %1;" : "=f"(y) : "f"(x));
    return y;
}
__device__ __forceinline__ float fast_rcp(float x) {
    float y;
    asm("rcp.approx.f32 %0, %1;" : "=f"(y) : "f"(x));
    return y;
}
// Eigen/XLA minimax rational tanh: deg-13/6, clamp ±7.9053, err ~1e-6.
// Cost: ~16 fma/alu issue slots + 1 MUFU.RCP (rt 8) -> runs on the idle fma pipe.
__device__ __forceinline__ float tanh_rat(float x) {
    float xc = fminf(fmaxf(x, -7.90531110763549f), 7.90531110763549f);
    float y = xc * xc;
    float p = -2.76076847742355e-16f;
    p = fmaf(p, y,  2.00018790482477e-13f);
    p = fmaf(p, y, -8.60467152213735e-11f);
    p = fmaf(p, y,  5.12229709037114e-08f);
    p = fmaf(p, y,  1.48572235717979e-05f);
    p = fmaf(p, y,  6.37261928875436e-04f);
    p = fmaf(p, y,  4.89352455891786e-03f);
    float q =  1.19825839466702e-06f;
    q = fmaf(q, y,  1.18534705686654e-04f);
    q = fmaf(q, y,  2.26843463243900e-03f);
    q = fmaf(q, y,  4.89352518554385e-03f);
    return xc * p * fast_rcp(q);
}
__device__ __forceinline__ uint32_t smem_u32(const void* p) {
    uint32_t a;
    asm("{ .reg .u64 t; cvta.to.shared.u64 t, %1; cvt.u32.u64 %0, t; }" : "=r"(a) : "l"(p));
    return a;
}
__device__ __forceinline__ void cp16(uint32_t dst, const void* src) {
    asm volatile("cp.async.cg.shared.global [%0], [%1], 16;" :: "r"(dst), "l"(src));
}
__device__ __forceinline__ void mma_bf16(float* c, const uint32_t* a, const uint32_t* b) {
    asm volatile(
        "mma.sync.aligned.m16n8k16.row.col.f32.bf16.bf16.f32 "
        "{%0,%1,%2,%3}, {%4,%5,%6,%7}, {%8,%9}, {%0,%1,%2,%3};"
        : "+f"(c[0]), "+f"(c[1]), "+f"(c[2]), "+f"(c[3])
        : "r"(a[0]), "r"(a[1]), "r"(a[2]), "r"(a[3]), "r"(b[0]), "r"(b[1]));
}

// ================= merged conversion kernel =================
#define CONV_A_BLOCKS (MROWS * HE / 4 / 512)     // 768
__global__ __launch_bounds__(512) void conv_all(const float* __restrict__ enc,
                                                const float* __restrict__ dec,
                                                const float* __restrict__ W,
                                                const float* __restrict__ U) {
    const int tid = threadIdx.x;
    if (blockIdx.x < CONV_A_BLOCKS) {
        int i = blockIdx.x * 512 + tid;
        int row = i / (HE / 4), q = i % (HE / 4);
        const float* src = row < BATCH * TE ? enc + row * HE
                                            : dec + (row - BATCH * TE) * HE;
        float4 v = *(const float4*)(src + 4 * q);
        float vv[4] = {v.x, v.y, v.z, v.w};
        __nv_bfloat16 h[4], l[4];
        #pragma unroll
        for (int j = 0; j < 4; j++) {
            h[j] = __float2bfloat16(vv[j]);
            l[j] = __float2bfloat16(vv[j] - __bfloat162float(h[j]));
        }
        *(uint64_t*)&g_Ah[i * 4] = *(uint64_t*)h;
        *(uint64_t*)&g_Al[i * 4] = *(uint64_t*)l;
    } else {
        __shared__ float t[32][33];
        int bb = blockIdx.x - CONV_A_BLOCKS;       // 0..511
        int z   = bb >> 8;                         // 0=W, 1=U
        int rem = bb & 255;
        int n0 = (rem & 15) * 32, k0 = (rem >> 4) * 32;
        const float* S = z ? U : W;
        int tx = tid & 31, ty = tid >> 5;          // (32,16)
        #pragma unroll
        for (int i = 0; i < 2; i++) {
            int r = ty + 16 * i;
            t[r][tx] = S[(k0 + r) * HE + n0 + tx];
        }
        __syncthreads();
        #pragma unroll
        for (int i = 0; i < 2; i++) {
            int n = ty + 16 * i;
            float v = t[tx][n];
            __nv_bfloat16 h = __float2bfloat16(v);
            __nv_bfloat16 l = __float2bfloat16(v - __bfloat162float(h));
            size_t o = (size_t)(z * HE + n0 + n) * HE + k0 + tx;
            g_Bh[o] = h;
            g_Bl[o] = l;
        }
    }
}

// ================= HMMA GEMM: 128x32 C tiles, 384 CTAs =================
#define BN       32
#define TA_B     (128 * 80)                  // 10240
#define TB_B     (BN * 80)                   //  2560
#define OFF_AH   0
#define OFF_AL   TA_B
#define OFF_BH   (2 * TA_B)
#define OFF_BL   (2 * TA_B + TB_B)
#define STAGEB   (2 * TA_B + 2 * TB_B)       // 25600
#define GEMM_SMEM (2 * STAGEB)               // 51200

__global__ __launch_bounds__(256) void gemm_tc() {
    extern __shared__ char smem[];
    const uint32_t sb = smem_u32(smem);
    const int tid = threadIdx.x;
    const int w = tid >> 5, lane = tid & 31;
    const int gid = lane >> 2, tig = lane & 3;
    const int mt = blockIdx.y, nt = blockIdx.x;      // mt 0..23, nt 0..15
    const int m0 = (mt < MT_WS ? mt : mt - MT_WS) * 128;
    const int aB = (mt < MT_WS ? 0 : BATCH * TE);
    const int bB = (mt < MT_WS ? 0 : HE);
    float* C = (mt < MT_WS ? g_Ws : g_Uh);
    const int n0 = nt * BN;
    const int wm = (w >> 1) * 32;            // 0,32,64,96
    const int wn = (w & 1) * 16;             // 0,16

    const int s_row0 = tid >> 2, s_q = tid & 3;               // 64 rows x 4 quads
    const uint32_t s_so0 = (uint32_t)(s_row0 * 80 + s_q * 16);

    float acc[2][2][4] = {};

    auto stage = [&](int c, int s) {
        uint32_t base = sb + s * STAGEB;
        #pragma unroll
        for (int t = 0; t < 2; t++) {
            uint32_t so = s_so0 + t * 64 * 80;
            size_t ga = (size_t)(aB + m0 + s_row0 + 64 * t) * HE + c * 32 + s_q * 8;
            cp16(base + OFF_AH + so, g_Ah + ga);
            cp16(base + OFF_AL + so, g_Al + ga);
        }
        if (s_row0 < BN) {
            size_t gb = (size_t)(bB + n0 + s_row0) * HE + c * 32 + s_q * 8;
            cp16(base + OFF_BH + s_so0, g_Bh + gb);
            cp16(base + OFF_BL + s_so0, g_Bl + gb);
        }
        asm volatile("cp.async.commit_group;" ::: "memory");
    };

    stage(0, 0);

    for (int c = 0; c < HE / 32; c++) {
        const int s = c & 1;
        if (c + 1 < HE / 32) {
            stage(c + 1, s ^ 1);
            asm volatile("cp.async.wait_group 1;" ::: "memory");
        } else {
            asm volatile("cp.async.wait_group 0;" ::: "memory");
        }
        __syncthreads();

        const char* tAh = smem + s * STAGEB + OFF_AH;
        const char* tAl = smem + s * STAGEB + OFF_AL;
        const char* tBh = smem + s * STAGEB + OFF_BH;
        const char* tBl = smem + s * STAGEB + OFF_BL;

        #pragma unroll
        for (int ks = 0; ks < 2; ks++) {
            const uint32_t kb = ks * 32 + 4 * tig;
            uint32_t aH[2][4], aL[2][4], bH[2][2], bL[2][2];
            #pragma unroll
            for (int mi = 0; mi < 2; mi++) {
                uint32_t ra = (uint32_t)((wm + mi * 16 + gid) * 80) + kb;
                aH[mi][0] = *(const uint32_t*)(tAh + ra);
                aH[mi][1] = *(const uint32_t*)(tAh + ra + 8 * 80);
                aH[mi][2] = *(const uint32_t*)(tAh + ra + 16);
                aH[mi][3] = *(const uint32_t*)(tAh + ra + 8 * 80 + 16);
                aL[mi][0] = *(const uint32_t*)(tAl + ra);
                aL[mi][1] = *(const uint32_t*)(tAl + ra + 8 * 80);
                aL[mi][2] = *(const uint32_t*)(tAl + ra + 16);
                aL[mi][3] = *(const uint32_t*)(tAl + ra + 8 * 80 + 16);
            }
            #pragma unroll
            for (int ni = 0; ni < 2; ni++) {
                uint32_t rb = (uint32_t)((wn + ni * 8 + gid) * 80) + kb;
                bH[ni][0] = *(const uint32_t*)(tBh + rb);
                bH[ni][1] = *(const uint32_t*)(tBh + rb + 16);
                bL[ni][0] = *(const uint32_t*)(tBl + rb);
                bL[ni][1] = *(const uint32_t*)(tBl + rb + 16);
            }
            #pragma unroll
            for (int mi = 0; mi < 2; mi++)
                #pragma unroll
                for (int ni = 0; ni < 2; ni++) {
                    mma_bf16(acc[mi][ni], aH[mi], bH[ni]);
                    mma_bf16(acc[mi][ni], aL[mi], bH[ni]);
                    mma_bf16(acc[mi][ni], aH[mi], bL[ni]);
                }
        }
        __syncthreads();
    }

    const int er = gid, ec = 2 * tig;
    #pragma unroll
    for (int mi = 0; mi < 2; mi++)
        #pragma unroll
        for (int ni = 0; ni < 2; ni++) {
            int row = m0 + wm + mi * 16 + er;
            int col = n0 + wn + ni * 8 + ec;
            *(float2*)&C[(size_t)row * HE + col] =
                make_float2(acc[mi][ni][0], acc[mi][ni][1]);
            *(float2*)&C[(size_t)(row + 8) * HE + col] =
                make_float2(acc[mi][ni][2], acc[mi][ni][3]);
        }
}

// ================= e-compute: dual-pipe tanh (MUFU + fma-pipe rational) ==========
__global__ __launch_bounds__(512) void e_comp(const float* __restrict__ V) {
    __shared__ float tile[2][HC][128 + 1];
    __shared__ float sV[HE];
    __shared__ float sU[DT * HE];

    const int tid = threadIdx.x;
    const int th = blockIdx.x;
    const int dg = blockIdx.y;
    const int b  = blockIdx.z;
    const int d0 = dg * DT;
    const int t  = tid & 127;
    const int dq = tid >> 7;

    for (int i = tid; i < HE; i += 512) sV[i] = V[i];
    for (int i = tid; i < DT * HE; i += 512)
        sU[i] = g_Uh[(b * TD + d0) * HE + i];
    const float* wsb = g_Ws + (size_t)(b * TE + th * 128) * HE;

    #pragma unroll
    for (int k = 0; k < 4; k++) {
        int i = tid + k * 512;
        int hh = i & (HC - 1), tt = i >> 4;
        tile[0][hh][tt] = wsb[tt * HE + hh];
    }
    __syncthreads();

    float e_acc[2] = {};
    float pre[4];

    for (int c = 0; c < HE / HC; c++) {
        const int buf = c & 1;
        if (c + 1 < HE / HC) {
            #pragma unroll
            for (int k = 0; k < 4; k++) {
                int i = tid + k * 512;
                int hh = i & (HC - 1), tt = i >> 4;
                pre[k] = wsb[tt * HE + (c + 1) * HC + hh];
            }
        }
        #pragma unroll
        for (int jj = 0; jj < HC; jj++) {
            float x = tile[buf][jj][t];
            float v = sV[c * HC + jj];
            if (jj & 1) {
                // fma-pipe stream: rational tanh (only RCP touches MUFU, rt 8)
                #pragma unroll
                for (int dd = 0; dd < 2; dd++) {
                    float u = sU[(dq * 2 + dd) * HE + c * HC + jj];
                    e_acc[dd] = fmaf(v, tanh_rat(x + u), e_acc[dd]);
                }
            } else {
                // MUFU stream: hardware tanh (rt 16)
                #pragma unroll
                for (int dd = 0; dd < 2; dd++) {
                    float u = sU[(dq * 2 + dd) * HE + c * HC + jj];
                    e_acc[dd] = fmaf(v, fast_tanh(x + u), e_acc[dd]);
                }
            }
        }
        if (c + 1 < HE / HC) {
            #pragma unroll
            for (int k = 0; k < 4; k++) {
                int i = tid + k * 512;
                int hh = i & (HC - 1), tt = i >> 4;
                tile[buf ^ 1][hh][tt] = pre[k];
            }
        }
        __syncthreads();
    }

    #pragma unroll
    for (int dd = 0; dd < 2; dd++)
        g_E[(size_t)(b * TD + d0 + dq * 2 + dd) * TE + th * 128 + t] = e_acc[dd];
}

// ================= fused softmax + context (round-13 shape) =====================
__global__ __launch_bounds__(512) void ctx_kernel(const float* __restrict__ enc,
                                                  float* __restrict__ outE,
                                                  float* __restrict__ outC) {
    __shared__ float  sE[DT][TE];            //  8 KB
    __shared__ float2 red2[3][DT][128];      // 24 KB

    const int tid = threadIdx.x;
    const int hh = blockIdx.x;
    const int dg = blockIdx.y;
    const int b  = blockIdx.z;
    const int d0 = dg * DT;

    for (int i = tid; i < DT * TE; i += 512)
        ((float*)sE)[i] = g_E[(size_t)(b * TD + d0) * TE + i];
    __syncthreads();

    // softmax: warp w (0..7) handles d = w
    {
        const int w = tid >> 5, lane = tid & 31;
        if (w < DT) {
            float vals[8];
            float m = -1e30f;
            #pragma unroll
            for (int i = 0; i < 8; i++) {
                vals[i] = sE[w][lane + 32 * i];
                m = fmaxf(m, vals[i]);
            }
            #pragma unroll
            for (int o = 16; o; o >>= 1) m = fmaxf(m, __shfl_xor_sync(0xffffffffu, m, o));
            float s = 0.f;
            #pragma unroll
            for (int i = 0; i < 8; i++) { vals[i] = __expf(vals[i] - m); s += vals[i]; }
            #pragma unroll
            for (int o = 16; o; o >>= 1) s += __shfl_xor_sync(0xffffffffu, s, o);
            float inv = 1.0f / s;
            float* oe = outE + (size_t)(b * TD + d0 + w) * TE;
            #pragma unroll
            for (int i = 0; i < 8; i++) {
                float ef = vals[i] * inv;
                sE[w][lane + 32 * i] = ef;
                if (hh == 0) oe[lane + 32 * i] = ef;
            }
        }
    }
    __syncthreads();

    const int hp = tid & 127;
    const int th = tid >> 7;                 // 0..3, each handles 64 t
    const float2* enc2 = (const float2*)(enc + (size_t)b * TE * HE);

    float2 acc[DT];
    #pragma unroll
    for (int d = 0; d < DT; d++) acc[d] = make_float2(0.f, 0.f);

    #pragma unroll 8
    for (int tt = 0; tt < TE / 4; tt++) {
        int t = th * (TE / 4) + tt;
        float2 v2 = enc2[t * (HE / 2) + hh * 128 + hp];
        #pragma unroll
        for (int d = 0; d < DT; d++) {
            float e = sE[d][t];
            acc[d].x = fmaf(e, v2.x, acc[d].x);
            acc[d].y = fmaf(e, v2.y, acc[d].y);
        }
    }

    if (th > 0) {
        #pragma unroll
        for (int d = 0; d < DT; d++) red2[th - 1][d][hp] = acc[d];
    }
    __syncthreads();
    if (th == 0) {
        #pragma unroll
        for (int d = 0; d < DT; d++) {
            float2 p0 = red2[0][d][hp], p1 = red2[1][d][hp], p2 = red2[2][d][hp];
            float2 o;
            o.x = acc[d].x + p0.x + p1.x + p2.x;
            o.y = acc[d].y + p0.y + p1.y + p2.y;
            ((float2*)(outC + (size_t)(b * TD + d0 + d) * HE))[hh * 128 + hp] = o;
        }
    }
}

// ================= launch =================
extern "C" void kernel_launch(void* const* d_in, const int* in_sizes, int n_in,
                              void* d_out, int out_size) {
    const float* enc = (const float*)d_in[0];
    const float* dec = (const float*)d_in[1];
    const float* W_a = (const float*)d_in[2];
    const float* U_a = (const float*)d_in[3];
    const float* V_a = (const float*)d_in[4];

    float* outC = (float*)d_out;
    float* outE = (float*)d_out + BATCH * TD * HE;

    cudaFuncSetAttribute(gemm_tc, cudaFuncAttributeMaxDynamicSharedMemorySize, GEMM_SMEM);

    conv_all<<<CONV_A_BLOCKS + 512, 512>>>(enc, dec, W_a, U_a);
    gemm_tc<<<dim3(HE / BN, MROWS / 128), 256, GEMM_SMEM>>>();
    e_comp<<<dim3(2, TD / DT, BATCH), 512>>>(V_a);
    ctx_kernel<<<dim3(2, TD / DT, BATCH), 512>>>(enc, outE, outC);
}

// round 15
// speedup vs baseline: 1.3259x; 1.3259x over previous
#include <cuda_runtime.h>
#include <cuda_bf16.h>
#include <cstdint>

#define BATCH 8
#define TE    256
#define TD    128
#define HE    512
#define HC    16
#define DT    8

#define MROWS (BATCH * TE + BATCH * TD)   // 3072 combined A rows
#define MT_WS (BATCH * TE / 128)          // 16 m-tiles for Ws

#define NSM    148
#define NUNITS 2048                        // 8 b x 16 dg(8d) x 16 tb(16t)

// ---------------- scratch ----------------
__device__ float g_Ws[BATCH * TE * HE];                     // enc @ W_a (raw)
__device__ float g_Uh[BATCH * TD * HE];                     // dec @ U_a (raw)
__device__ float g_E [BATCH * TD * TE];                     // raw logits
__device__ __align__(16) __nv_bfloat16 g_Ah[MROWS * HE];
__device__ __align__(16) __nv_bfloat16 g_Al[MROWS * HE];
__device__ __align__(16) __nv_bfloat16 g_Bh[2 * HE * HE];
__device__ __align__(16) __nv_bfloat16 g_Bl[2 * HE * HE];

__device__ __forceinline__ float fast_tanh(float x) {
    float y;
    asm("tanh.approx.f32 %0, %1;" : "=f"(y) : "f"(x));
    return y;
}
__device__ __forceinline__ uint32_t smem_u32(const void* p) {
    uint32_t a;
    asm("{ .reg .u64 t; cvta.to.shared.u64 t, %1; cvt.u32.u64 %0, t; }" : "=r"(a) : "l"(p));
    return a;
}
__device__ __forceinline__ void cp16(uint32_t dst, const void* src) {
    asm volatile("cp.async.cg.shared.global [%0], [%1], 16;" :: "r"(dst), "l"(src));
}
__device__ __forceinline__ void mma_bf16(float* c, const uint32_t* a, const uint32_t* b) {
    asm volatile(
        "mma.sync.aligned.m16n8k16.row.col.f32.bf16.bf16.f32 "
        "{%0,%1,%2,%3}, {%4,%5,%6,%7}, {%8,%9}, {%0,%1,%2,%3};"
        : "+f"(c[0]), "+f"(c[1]), "+f"(c[2]), "+f"(c[3])
        : "r"(a[0]), "r"(a[1]), "r"(a[2]), "r"(a[3]), "r"(b[0]), "r"(b[1]));
}

// ================= merged conversion kernel (unchanged) =================
#define CONV_A_BLOCKS (MROWS * HE / 4 / 512)     // 768
__global__ __launch_bounds__(512) void conv_all(const float* __restrict__ enc,
                                                const float* __restrict__ dec,
                                                const float* __restrict__ W,
                                                const float* __restrict__ U) {
    const int tid = threadIdx.x;
    if (blockIdx.x < CONV_A_BLOCKS) {
        int i = blockIdx.x * 512 + tid;
        int row = i / (HE / 4), q = i % (HE / 4);
        const float* src = row < BATCH * TE ? enc + row * HE
                                            : dec + (row - BATCH * TE) * HE;
        float4 v = *(const float4*)(src + 4 * q);
        float vv[4] = {v.x, v.y, v.z, v.w};
        __nv_bfloat16 h[4], l[4];
        #pragma unroll
        for (int j = 0; j < 4; j++) {
            h[j] = __float2bfloat16(vv[j]);
            l[j] = __float2bfloat16(vv[j] - __bfloat162float(h[j]));
        }
        *(uint64_t*)&g_Ah[i * 4] = *(uint64_t*)h;
        *(uint64_t*)&g_Al[i * 4] = *(uint64_t*)l;
    } else {
        __shared__ float t[32][33];
        int bb = blockIdx.x - CONV_A_BLOCKS;       // 0..511
        int z   = bb >> 8;                         // 0=W, 1=U
        int rem = bb & 255;
        int n0 = (rem & 15) * 32, k0 = (rem >> 4) * 32;
        const float* S = z ? U : W;
        int tx = tid & 31, ty = tid >> 5;          // (32,16)
        #pragma unroll
        for (int i = 0; i < 2; i++) {
            int r = ty + 16 * i;
            t[r][tx] = S[(k0 + r) * HE + n0 + tx];
        }
        __syncthreads();
        #pragma unroll
        for (int i = 0; i < 2; i++) {
            int n = ty + 16 * i;
            float v = t[tx][n];
            __nv_bfloat16 h = __float2bfloat16(v);
            __nv_bfloat16 l = __float2bfloat16(v - __bfloat162float(h));
            size_t o = (size_t)(z * HE + n0 + n) * HE + k0 + tx;
            g_Bh[o] = h;
            g_Bl[o] = l;
        }
    }
}

// ================= HMMA GEMM: 128x32 C tiles, 384 CTAs (unchanged) ===============
#define BN       32
#define TA_B     (128 * 80)                  // 10240
#define TB_B     (BN * 80)                   //  2560
#define OFF_AH   0
#define OFF_AL   TA_B
#define OFF_BH   (2 * TA_B)
#define OFF_BL   (2 * TA_B + TB_B)
#define STAGEB   (2 * TA_B + 2 * TB_B)       // 25600
#define GEMM_SMEM (2 * STAGEB)               // 51200

__global__ __launch_bounds__(256) void gemm_tc() {
    extern __shared__ char smem[];
    const uint32_t sb = smem_u32(smem);
    const int tid = threadIdx.x;
    const int w = tid >> 5, lane = tid & 31;
    const int gid = lane >> 2, tig = lane & 3;
    const int mt = blockIdx.y, nt = blockIdx.x;      // mt 0..23, nt 0..15
    const int m0 = (mt < MT_WS ? mt : mt - MT_WS) * 128;
    const int aB = (mt < MT_WS ? 0 : BATCH * TE);
    const int bB = (mt < MT_WS ? 0 : HE);
    float* C = (mt < MT_WS ? g_Ws : g_Uh);
    const int n0 = nt * BN;
    const int wm = (w >> 1) * 32;
    const int wn = (w & 1) * 16;

    const int s_row0 = tid >> 2, s_q = tid & 3;
    const uint32_t s_so0 = (uint32_t)(s_row0 * 80 + s_q * 16);

    float acc[2][2][4] = {};

    auto stage = [&](int c, int s) {
        uint32_t base = sb + s * STAGEB;
        #pragma unroll
        for (int t = 0; t < 2; t++) {
            uint32_t so = s_so0 + t * 64 * 80;
            size_t ga = (size_t)(aB + m0 + s_row0 + 64 * t) * HE + c * 32 + s_q * 8;
            cp16(base + OFF_AH + so, g_Ah + ga);
            cp16(base + OFF_AL + so, g_Al + ga);
        }
        if (s_row0 < BN) {
            size_t gb = (size_t)(bB + n0 + s_row0) * HE + c * 32 + s_q * 8;
            cp16(base + OFF_BH + s_so0, g_Bh + gb);
            cp16(base + OFF_BL + s_so0, g_Bl + gb);
        }
        asm volatile("cp.async.commit_group;" ::: "memory");
    };

    stage(0, 0);

    for (int c = 0; c < HE / 32; c++) {
        const int s = c & 1;
        if (c + 1 < HE / 32) {
            stage(c + 1, s ^ 1);
            asm volatile("cp.async.wait_group 1;" ::: "memory");
        } else {
            asm volatile("cp.async.wait_group 0;" ::: "memory");
        }
        __syncthreads();

        const char* tAh = smem + s * STAGEB + OFF_AH;
        const char* tAl = smem + s * STAGEB + OFF_AL;
        const char* tBh = smem + s * STAGEB + OFF_BH;
        const char* tBl = smem + s * STAGEB + OFF_BL;

        #pragma unroll
        for (int ks = 0; ks < 2; ks++) {
            const uint32_t kb = ks * 32 + 4 * tig;
            uint32_t aH[2][4], aL[2][4], bH[2][2], bL[2][2];
            #pragma unroll
            for (int mi = 0; mi < 2; mi++) {
                uint32_t ra = (uint32_t)((wm + mi * 16 + gid) * 80) + kb;
                aH[mi][0] = *(const uint32_t*)(tAh + ra);
                aH[mi][1] = *(const uint32_t*)(tAh + ra + 8 * 80);
                aH[mi][2] = *(const uint32_t*)(tAh + ra + 16);
                aH[mi][3] = *(const uint32_t*)(tAh + ra + 8 * 80 + 16);
                aL[mi][0] = *(const uint32_t*)(tAl + ra);
                aL[mi][1] = *(const uint32_t*)(tAl + ra + 8 * 80);
                aL[mi][2] = *(const uint32_t*)(tAl + ra + 16);
                aL[mi][3] = *(const uint32_t*)(tAl + ra + 8 * 80 + 16);
            }
            #pragma unroll
            for (int ni = 0; ni < 2; ni++) {
                uint32_t rb = (uint32_t)((wn + ni * 8 + gid) * 80) + kb;
                bH[ni][0] = *(const uint32_t*)(tBh + rb);
                bH[ni][1] = *(const uint32_t*)(tBh + rb + 16);
                bL[ni][0] = *(const uint32_t*)(tBl + rb);
                bL[ni][1] = *(const uint32_t*)(tBl + rb + 16);
            }
            #pragma unroll
            for (int mi = 0; mi < 2; mi++)
                #pragma unroll
                for (int ni = 0; ni < 2; ni++) {
                    mma_bf16(acc[mi][ni], aH[mi], bH[ni]);
                    mma_bf16(acc[mi][ni], aL[mi], bH[ni]);
                    mma_bf16(acc[mi][ni], aH[mi], bL[ni]);
                }
        }
        __syncthreads();
    }

    const int er = gid, ec = 2 * tig;
    #pragma unroll
    for (int mi = 0; mi < 2; mi++)
        #pragma unroll
        for (int ni = 0; ni < 2; ni++) {
            int row = m0 + wm + mi * 16 + er;
            int col = n0 + wn + ni * 8 + ec;
            *(float2*)&C[(size_t)row * HE + col] =
                make_float2(acc[mi][ni][0], acc[mi][ni][1]);
            *(float2*)&C[(size_t)(row + 8) * HE + col] =
                make_float2(acc[mi][ni][2], acc[mi][ni][3]);
        }
}

// ================= e-compute: persistent, fine-grained, balanced ================
// 148 blocks x 512 threads. Unit = (b, dg of 8 d, tb of 16 t): 2048 units,
// statically partitioned (13-14 per block -> 99% MUFU balance vs 86.5%).
// Thread: cell = tid&127 -> (t = cell&15, d = cell>>4); hq = tid>>7 h-quarter.
// Ws tiles prefetched cross-chunk/cross-unit via registers (round-13 pattern).
__global__ __launch_bounds__(512) void e_comp(const float* __restrict__ V) {
    __shared__ float tile[2][16][129];       // 16.1 KB, pitch 129: conflict-free
    __shared__ float sU[8][512];             // 16 KB
    __shared__ float sV[512];                //  2 KB
    __shared__ float red[3][128];            // 1.5 KB

    const int tid  = threadIdx.x;
    const int cell = tid & 127;
    const int t    = cell & 15;
    const int d    = cell >> 4;              // 0..7
    const int hq   = tid >> 7;               // 0..3

    const int u0 = (int)(((long long)blockIdx.x * NUNITS) / NSM);
    const int u1 = (int)(((long long)(blockIdx.x + 1) * NUNITS) / NSM);

    sV[tid] = V[tid];

    // ---- prologue: decode u0, load its sU and chunk 0 ----
    int pb  = u0 >> 8;
    int pr  = u0 & 255;
    int pdg = pr >> 4, ptb = pr & 15;
    {
        const float* up = g_Uh + (size_t)(pb * TD + pdg * 8) * HE;
        #pragma unroll
        for (int k = 0; k < 8; k++) {
            int i = tid + k * 512;
            sU[i >> 9][i & 511] = up[i];
        }
        const float* wsb = g_Ws + ((size_t)(pb * TE) + ptb * 16) * HE;
        #pragma unroll
        for (int k = 0; k < 4; k++) {
            int i = tid + k * 512;
            int hl = i & 127, tt = i >> 7;
            tile[0][tt][hl] = wsb[(size_t)tt * HE + hl];
        }
    }
    __syncthreads();

    int prev_bd = (pb << 4) | pdg;
    const float* sUd = sU[d];
    float pre[4];

    for (int u = u0; u < u1; u++) {
        const int b  = u >> 8;
        const int r  = u & 255;
        const int dg = r >> 4;
        const int tb = r & 15;
        const float* wsb = g_Ws + ((size_t)(b * TE) + tb * 16) * HE;

        const int bd = (b << 4) | dg;
        if (bd != prev_bd) {                  // uniform branch (u uniform per block)
            const float* up = g_Uh + (size_t)(b * TD + dg * 8) * HE;
            #pragma unroll
            for (int k = 0; k < 8; k++) {
                int i = tid + k * 512;
                sU[i >> 9][i & 511] = up[i];
            }
            prev_bd = bd;
            __syncthreads();
        }

        float e = 0.f;
        #pragma unroll
        for (int c = 0; c < 4; c++) {
            const int buf = c & 1;
            // prefetch next chunk (same unit c+1, or next unit's chunk 0)
            bool has_next;
            const float* nw;
            int nc;
            if (c < 3) { has_next = true; nw = wsb; nc = c + 1; }
            else if (u + 1 < u1) {
                int nb = (u + 1) >> 8, nr = (u + 1) & 255, ntb = nr & 15;
                nw = g_Ws + ((size_t)(nb * TE) + ntb * 16) * HE;
                nc = 0; has_next = true;
            } else { has_next = false; nw = wsb; nc = 0; }

            if (has_next) {
                #pragma unroll
                for (int k = 0; k < 4; k++) {
                    int i = tid + k * 512;
                    int hl = i & 127, tt = i >> 7;
                    pre[k] = nw[(size_t)tt * HE + nc * 128 + hl];
                }
            }
            // compute: 32 h per thread, MUFU-bound
            #pragma unroll
            for (int jj = 0; jj < 32; jj++) {
                int h = hq * 32 + jj;                 // within chunk
                float x  = tile[buf][t][h];           // 16-distinct, 2-way bcast
                float uu = sUd[c * 128 + h];          // broadcast
                float vv = sV[c * 128 + h];           // broadcast
                e = fmaf(vv, fast_tanh(x + uu), e);
            }
            if (has_next) {
                #pragma unroll
                for (int k = 0; k < 4; k++) {
                    int i = tid + k * 512;
                    int hl = i & 127, tt = i >> 7;
                    tile[buf ^ 1][tt][hl] = pre[k];
                }
            }
            __syncthreads();
        }

        // reduce the 4 h-quarters -> g_E
        if (hq > 0) red[hq - 1][cell] = e;
        __syncthreads();
        if (hq == 0) {
            float tot = e + red[0][cell] + red[1][cell] + red[2][cell];
            g_E[(size_t)(b * TD + dg * 8 + d) * TE + tb * 16 + t] = tot;
        }
    }
}

// ================= fused softmax + context (round-13 shape, unchanged) ==========
__global__ __launch_bounds__(512) void ctx_kernel(const float* __restrict__ enc,
                                                  float* __restrict__ outE,
                                                  float* __restrict__ outC) {
    __shared__ float  sE[DT][TE];            //  8 KB
    __shared__ float2 red2[3][DT][128];      // 24 KB

    const int tid = threadIdx.x;
    const int hh = blockIdx.x;
    const int dg = blockIdx.y;
    const int b  = blockIdx.z;
    const int d0 = dg * DT;

    for (int i = tid; i < DT * TE; i += 512)
        ((float*)sE)[i] = g_E[(size_t)(b * TD + d0) * TE + i];
    __syncthreads();

    {
        const int w = tid >> 5, lane = tid & 31;
        if (w < DT) {
            float vals[8];
            float m = -1e30f;
            #pragma unroll
            for (int i = 0; i < 8; i++) {
                vals[i] = sE[w][lane + 32 * i];
                m = fmaxf(m, vals[i]);
            }
            #pragma unroll
            for (int o = 16; o; o >>= 1) m = fmaxf(m, __shfl_xor_sync(0xffffffffu, m, o));
            float s = 0.f;
            #pragma unroll
            for (int i = 0; i < 8; i++) { vals[i] = __expf(vals[i] - m); s += vals[i]; }
            #pragma unroll
            for (int o = 16; o; o >>= 1) s += __shfl_xor_sync(0xffffffffu, s, o);
            float inv = 1.0f / s;
            float* oe = outE + (size_t)(b * TD + d0 + w) * TE;
            #pragma unroll
            for (int i = 0; i < 8; i++) {
                float ef = vals[i] * inv;
                sE[w][lane + 32 * i] = ef;
                if (hh == 0) oe[lane + 32 * i] = ef;
            }
        }
    }
    __syncthreads();

    const int hp = tid & 127;
    const int th = tid >> 7;
    const float2* enc2 = (const float2*)(enc + (size_t)b * TE * HE);

    float2 acc[DT];
    #pragma unroll
    for (int d = 0; d < DT; d++) acc[d] = make_float2(0.f, 0.f);

    #pragma unroll 8
    for (int tt = 0; tt < TE / 4; tt++) {
        int t = th * (TE / 4) + tt;
        float2 v2 = enc2[t * (HE / 2) + hh * 128 + hp];
        #pragma unroll
        for (int d = 0; d < DT; d++) {
            float e = sE[d][t];
            acc[d].x = fmaf(e, v2.x, acc[d].x);
            acc[d].y = fmaf(e, v2.y, acc[d].y);
        }
    }

    if (th > 0) {
        #pragma unroll
        for (int d = 0; d < DT; d++) red2[th - 1][d][hp] = acc[d];
    }
    __syncthreads();
    if (th == 0) {
        #pragma unroll
        for (int d = 0; d < DT; d++) {
            float2 p0 = red2[0][d][hp], p1 = red2[1][d][hp], p2 = red2[2][d][hp];
            float2 o;
            o.x = acc[d].x + p0.x + p1.x + p2.x;
            o.y = acc[d].y + p0.y + p1.y + p2.y;
            ((float2*)(outC + (size_t)(b * TD + d0 + d) * HE))[hh * 128 + hp] = o;
        }
    }
}

// ================= launch =================
extern "C" void kernel_launch(void* const* d_in, const int* in_sizes, int n_in,
                              void* d_out, int out_size) {
    const float* enc = (const float*)d_in[0];
    const float* dec = (const float*)d_in[1];
    const float* W_a = (const float*)d_in[2];
    const float* U_a = (const float*)d_in[3];
    const float* V_a = (const float*)d_in[4];

    float* outC = (float*)d_out;
    float* outE = (float*)d_out + BATCH * TD * HE;

    cudaFuncSetAttribute(gemm_tc, cudaFuncAttributeMaxDynamicSharedMemorySize, GEMM_SMEM);

    conv_all<<<CONV_A_BLOCKS + 512, 512>>>(enc, dec, W_a, U_a);
    gemm_tc<<<dim3(HE / BN, MROWS / 128), 256, GEMM_SMEM>>>();
    e_comp<<<NSM, 512>>>(V_a);
    ctx_kernel<<<dim3(2, TD / DT, BATCH), 512>>>(enc, outE, outC);
}

// round 16
// speedup vs baseline: 1.3629x; 1.0279x over previous
#include <cuda_runtime.h>
#include <cuda_bf16.h>
#include <cstdint>

#define BATCH 8
#define TE    256
#define TD    128
#define HE    512
#define HC    16
#define DT    8

#define MROWS (BATCH * TE + BATCH * TD)   // 3072 combined A rows
#define MT_WS (BATCH * TE / 128)          // 16 m-tiles for Ws

// ---------------- scratch ----------------
__device__ float g_Ws[BATCH * TE * HE];                     // enc @ W_a (raw)
__device__ float g_Uh[BATCH * TD * HE];                     // dec @ U_a (raw)
__device__ float g_E [BATCH * TD * TE];                     // raw logits
__device__ __align__(16) __nv_bfloat16 g_Ah[MROWS * HE];
__device__ __align__(16) __nv_bfloat16 g_Al[MROWS * HE];
__device__ __align__(16) __nv_bfloat16 g_Bh[2 * HE * HE];
__device__ __align__(16) __nv_bfloat16 g_Bl[2 * HE * HE];
__device__ __align__(16) __nv_bfloat16 g_eH[BATCH * TD * TE];   // softmax(e) hi
__device__ __align__(16) __nv_bfloat16 g_eL[BATCH * TD * TE];   // softmax(e) lo
__device__ __align__(16) __nv_bfloat16 g_Th[BATCH * HE * TE];   // enc^T hi [b][h][t]
__device__ __align__(16) __nv_bfloat16 g_Tl[BATCH * HE * TE];   // enc^T lo

__device__ __forceinline__ float fast_tanh(float x) {
    float y;
    asm("tanh.approx.f32 %0, %1;" : "=f"(y) : "f"(x));
    return y;
}
__device__ __forceinline__ uint32_t smem_u32(const void* p) {
    uint32_t a;
    asm("{ .reg .u64 t; cvta.to.shared.u64 t, %1; cvt.u32.u64 %0, t; }" : "=r"(a) : "l"(p));
    return a;
}
__device__ __forceinline__ void cp16(uint32_t dst, const void* src) {
    asm volatile("cp.async.cg.shared.global [%0], [%1], 16;" :: "r"(dst), "l"(src));
}
__device__ __forceinline__ void mma_bf16(float* c, const uint32_t* a, const uint32_t* b) {
    asm volatile(
        "mma.sync.aligned.m16n8k16.row.col.f32.bf16.bf16.f32 "
        "{%0,%1,%2,%3}, {%4,%5,%6,%7}, {%8,%9}, {%0,%1,%2,%3};"
        : "+f"(c[0]), "+f"(c[1]), "+f"(c[2]), "+f"(c[3])
        : "r"(a[0]), "r"(a[1]), "r"(a[2]), "r"(a[3]), "r"(b[0]), "r"(b[1]));
}

// ================= merged conversion kernel (+ enc transpose) =================
// [0,768): A hi/lo split. [768,1280): W/U transpose+split. [1280,2304): enc^T hi/lo.
#define CONV_A_BLOCKS (MROWS * HE / 4 / 512)     // 768
__global__ __launch_bounds__(512) void conv_all(const float* __restrict__ enc,
                                                const float* __restrict__ dec,
                                                const float* __restrict__ W,
                                                const float* __restrict__ U) {
    const int tid = threadIdx.x;
    if (blockIdx.x < CONV_A_BLOCKS) {
        int i = blockIdx.x * 512 + tid;
        int row = i / (HE / 4), q = i % (HE / 4);
        const float* src = row < BATCH * TE ? enc + row * HE
                                            : dec + (row - BATCH * TE) * HE;
        float4 v = *(const float4*)(src + 4 * q);
        float vv[4] = {v.x, v.y, v.z, v.w};
        __nv_bfloat16 h[4], l[4];
        #pragma unroll
        for (int j = 0; j < 4; j++) {
            h[j] = __float2bfloat16(vv[j]);
            l[j] = __float2bfloat16(vv[j] - __bfloat162float(h[j]));
        }
        *(uint64_t*)&g_Ah[i * 4] = *(uint64_t*)h;
        *(uint64_t*)&g_Al[i * 4] = *(uint64_t*)l;
    } else if (blockIdx.x < CONV_A_BLOCKS + 512) {
        __shared__ float t[32][33];
        int bb = blockIdx.x - CONV_A_BLOCKS;       // 0..511
        int z   = bb >> 8;                         // 0=W, 1=U
        int rem = bb & 255;
        int n0 = (rem & 15) * 32, k0 = (rem >> 4) * 32;
        const float* S = z ? U : W;
        int tx = tid & 31, ty = tid >> 5;          // (32,16)
        #pragma unroll
        for (int i = 0; i < 2; i++) {
            int r = ty + 16 * i;
            t[r][tx] = S[(k0 + r) * HE + n0 + tx];
        }
        __syncthreads();
        #pragma unroll
        for (int i = 0; i < 2; i++) {
            int n = ty + 16 * i;
            float v = t[tx][n];
            __nv_bfloat16 h = __float2bfloat16(v);
            __nv_bfloat16 l = __float2bfloat16(v - __bfloat162float(h));
            size_t o = (size_t)(z * HE + n0 + n) * HE + k0 + tx;
            g_Bh[o] = h;
            g_Bl[o] = l;
        }
    } else {
        // enc^T: 1024 blocks = 8 b x 16 h-tiles x 8 t-tiles of 32x32
        __shared__ float t[32][33];
        int bb  = blockIdx.x - CONV_A_BLOCKS - 512;   // 0..1023
        int b   = bb >> 7;
        int rem = bb & 127;
        int h0 = (rem >> 3) * 32, t0 = (rem & 7) * 32;
        int tx = tid & 31, ty = tid >> 5;             // (32,16)
        #pragma unroll
        for (int i = 0; i < 2; i++) {
            int r = ty + 16 * i;                      // t within tile
            t[r][tx] = enc[((size_t)(b * TE) + t0 + r) * HE + h0 + tx];
        }
        __syncthreads();
        #pragma unroll
        for (int i = 0; i < 2; i++) {
            int hl = ty + 16 * i;                     // h within tile
            float v = t[tx][hl];                      // = enc[t0+tx][h0+hl]
            __nv_bfloat16 h = __float2bfloat16(v);
            __nv_bfloat16 l = __float2bfloat16(v - __bfloat162float(h));
            size_t o = ((size_t)(b * HE) + h0 + hl) * TE + t0 + tx;   // coalesced
            g_Th[o] = h;
            g_Tl[o] = l;
        }
    }
}

// ================= HMMA GEMM: 128x32 C tiles, 384 CTAs (unchanged) ===============
#define BN       32
#define TA_B     (128 * 80)                  // 10240
#define TB_B     (BN * 80)                   //  2560
#define OFF_AH   0
#define OFF_AL   TA_B
#define OFF_BH   (2 * TA_B)
#define OFF_BL   (2 * TA_B + TB_B)
#define STAGEB   (2 * TA_B + 2 * TB_B)       // 25600
#define GEMM_SMEM (2 * STAGEB)               // 51200

__global__ __launch_bounds__(256) void gemm_tc() {
    extern __shared__ char smem[];
    const uint32_t sb = smem_u32(smem);
    const int tid = threadIdx.x;
    const int w = tid >> 5, lane = tid & 31;
    const int gid = lane >> 2, tig = lane & 3;
    const int mt = blockIdx.y, nt = blockIdx.x;
    const int m0 = (mt < MT_WS ? mt : mt - MT_WS) * 128;
    const int aB = (mt < MT_WS ? 0 : BATCH * TE);
    const int bB = (mt < MT_WS ? 0 : HE);
    float* C = (mt < MT_WS ? g_Ws : g_Uh);
    const int n0 = nt * BN;
    const int wm = (w >> 1) * 32;
    const int wn = (w & 1) * 16;

    const int s_row0 = tid >> 2, s_q = tid & 3;
    const uint32_t s_so0 = (uint32_t)(s_row0 * 80 + s_q * 16);

    float acc[2][2][4] = {};

    auto stage = [&](int c, int s) {
        uint32_t base = sb + s * STAGEB;
        #pragma unroll
        for (int t = 0; t < 2; t++) {
            uint32_t so = s_so0 + t * 64 * 80;
            size_t ga = (size_t)(aB + m0 + s_row0 + 64 * t) * HE + c * 32 + s_q * 8;
            cp16(base + OFF_AH + so, g_Ah + ga);
            cp16(base + OFF_AL + so, g_Al + ga);
        }
        if (s_row0 < BN) {
            size_t gb = (size_t)(bB + n0 + s_row0) * HE + c * 32 + s_q * 8;
            cp16(base + OFF_BH + s_so0, g_Bh + gb);
            cp16(base + OFF_BL + s_so0, g_Bl + gb);
        }
        asm volatile("cp.async.commit_group;" ::: "memory");
    };

    stage(0, 0);

    for (int c = 0; c < HE / 32; c++) {
        const int s = c & 1;
        if (c + 1 < HE / 32) {
            stage(c + 1, s ^ 1);
            asm volatile("cp.async.wait_group 1;" ::: "memory");
        } else {
            asm volatile("cp.async.wait_group 0;" ::: "memory");
        }
        __syncthreads();

        const char* tAh = smem + s * STAGEB + OFF_AH;
        const char* tAl = smem + s * STAGEB + OFF_AL;
        const char* tBh = smem + s * STAGEB + OFF_BH;
        const char* tBl = smem + s * STAGEB + OFF_BL;

        #pragma unroll
        for (int ks = 0; ks < 2; ks++) {
            const uint32_t kb = ks * 32 + 4 * tig;
            uint32_t aH[2][4], aL[2][4], bH[2][2], bL[2][2];
            #pragma unroll
            for (int mi = 0; mi < 2; mi++) {
                uint32_t ra = (uint32_t)((wm + mi * 16 + gid) * 80) + kb;
                aH[mi][0] = *(const uint32_t*)(tAh + ra);
                aH[mi][1] = *(const uint32_t*)(tAh + ra + 8 * 80);
                aH[mi][2] = *(const uint32_t*)(tAh + ra + 16);
                aH[mi][3] = *(const uint32_t*)(tAh + ra + 8 * 80 + 16);
                aL[mi][0] = *(const uint32_t*)(tAl + ra);
                aL[mi][1] = *(const uint32_t*)(tAl + ra + 8 * 80);
                aL[mi][2] = *(const uint32_t*)(tAl + ra + 16);
                aL[mi][3] = *(const uint32_t*)(tAl + ra + 8 * 80 + 16);
            }
            #pragma unroll
            for (int ni = 0; ni < 2; ni++) {
                uint32_t rb = (uint32_t)((wn + ni * 8 + gid) * 80) + kb;
                bH[ni][0] = *(const uint32_t*)(tBh + rb);
                bH[ni][1] = *(const uint32_t*)(tBh + rb + 16);
                bL[ni][0] = *(const uint32_t*)(tBl + rb);
                bL[ni][1] = *(const uint32_t*)(tBl + rb + 16);
            }
            #pragma unroll
            for (int mi = 0; mi < 2; mi++)
                #pragma unroll
                for (int ni = 0; ni < 2; ni++) {
                    mma_bf16(acc[mi][ni], aH[mi], bH[ni]);
                    mma_bf16(acc[mi][ni], aL[mi], bH[ni]);
                    mma_bf16(acc[mi][ni], aH[mi], bL[ni]);
                }
        }
        __syncthreads();
    }

    const int er = gid, ec = 2 * tig;
    #pragma unroll
    for (int mi = 0; mi < 2; mi++)
        #pragma unroll
        for (int ni = 0; ni < 2; ni++) {
            int row = m0 + wm + mi * 16 + er;
            int col = n0 + wn + ni * 8 + ec;
            *(float2*)&C[(size_t)row * HE + col] =
                make_float2(acc[mi][ni][0], acc[mi][ni][1]);
            *(float2*)&C[(size_t)(row + 8) * HE + col] =
                make_float2(acc[mi][ni][2], acc[mi][ni][3]);
        }
}

// ================= e-compute: round-13 exact (at MUFU.TANH floor) ================
__global__ __launch_bounds__(512) void e_comp(const float* __restrict__ V) {
    __shared__ float tile[2][HC][128 + 1];
    __shared__ float sV[HE];
    __shared__ float sU[DT * HE];

    const int tid = threadIdx.x;
    const int th = blockIdx.x;
    const int dg = blockIdx.y;
    const int b  = blockIdx.z;
    const int d0 = dg * DT;
    const int t  = tid & 127;
    const int dq = tid >> 7;

    for (int i = tid; i < HE; i += 512) sV[i] = V[i];
    for (int i = tid; i < DT * HE; i += 512)
        sU[i] = g_Uh[(b * TD + d0) * HE + i];
    const float* wsb = g_Ws + (size_t)(b * TE + th * 128) * HE;

    #pragma unroll
    for (int k = 0; k < 4; k++) {
        int i = tid + k * 512;
        int hh = i & (HC - 1), tt = i >> 4;
        tile[0][hh][tt] = wsb[tt * HE + hh];
    }
    __syncthreads();

    float e_acc[2] = {};
    float pre[4];

    for (int c = 0; c < HE / HC; c++) {
        const int buf = c & 1;
        if (c + 1 < HE / HC) {
            #pragma unroll
            for (int k = 0; k < 4; k++) {
                int i = tid + k * 512;
                int hh = i & (HC - 1), tt = i >> 4;
                pre[k] = wsb[tt * HE + (c + 1) * HC + hh];
            }
        }
        #pragma unroll
        for (int jj = 0; jj < HC; jj++) {
            float x = tile[buf][jj][t];
            float v = sV[c * HC + jj];
            #pragma unroll
            for (int dd = 0; dd < 2; dd++) {
                float u = sU[(dq * 2 + dd) * HE + c * HC + jj];
                e_acc[dd] = fmaf(v, fast_tanh(x + u), e_acc[dd]);
            }
        }
        if (c + 1 < HE / HC) {
            #pragma unroll
            for (int k = 0; k < 4; k++) {
                int i = tid + k * 512;
                int hh = i & (HC - 1), tt = i >> 4;
                tile[buf ^ 1][hh][tt] = pre[k];
            }
        }
        __syncthreads();
    }

    #pragma unroll
    for (int dd = 0; dd < 2; dd++)
        g_E[(size_t)(b * TD + d0 + dq * 2 + dd) * TE + th * 128 + t] = e_acc[dd];
}

// ================= softmax + bf16 hi/lo conversion =================
// grid (16, 8), 256 threads: warp w handles d = blockIdx.x*8 + w.
__global__ __launch_bounds__(256) void softmax_cvt(float* __restrict__ outE) {
    const int tid = threadIdx.x;
    const int w = tid >> 5, lane = tid & 31;
    const int d = blockIdx.x * DT + w;
    const int b = blockIdx.y;
    const size_t base = (size_t)(b * TD + d) * TE;
    const float* e = g_E + base;

    float vals[8];
    float m = -1e30f;
    #pragma unroll
    for (int i = 0; i < 8; i++) {
        vals[i] = e[lane + 32 * i];
        m = fmaxf(m, vals[i]);
    }
    #pragma unroll
    for (int o = 16; o; o >>= 1) m = fmaxf(m, __shfl_xor_sync(0xffffffffu, m, o));
    float s = 0.f;
    #pragma unroll
    for (int i = 0; i < 8; i++) { vals[i] = __expf(vals[i] - m); s += vals[i]; }
    #pragma unroll
    for (int o = 16; o; o >>= 1) s += __shfl_xor_sync(0xffffffffu, s, o);
    float inv = 1.0f / s;
    #pragma unroll
    for (int i = 0; i < 8; i++) {
        float ef = vals[i] * inv;
        outE[base + lane + 32 * i] = ef;
        __nv_bfloat16 h = __float2bfloat16(ef);
        __nv_bfloat16 l = __float2bfloat16(ef - __bfloat162float(h));
        g_eH[base + lane + 32 * i] = h;
        g_eL[base + lane + 32 * i] = l;
    }
}

// ================= ctx via HMMA: c[d,h] = e @ enc  (3-pass compensated) ==========
// Per batch: [128 d x 256 t] @ [256 t x 512 h]. C tile 128x64, grid (8 nt, 8 b).
#define CBN      64
#define CTA_B    (128 * 80)                  // 10240 (A: 128 d rows)
#define CTB_B    (CBN * 80)                  //  5120 (B: 64 h rows)
#define COFF_AH  0
#define COFF_AL  CTA_B
#define COFF_BH  (2 * CTA_B)
#define COFF_BL  (2 * CTA_B + CTB_B)
#define CSTAGE   (2 * CTA_B + 2 * CTB_B)     // 30720
#define CTX_SMEM (2 * CSTAGE)                // 61440

__global__ __launch_bounds__(256) void ctx_mma(float* __restrict__ outC) {
    extern __shared__ char smem[];
    const uint32_t sb = smem_u32(smem);
    const int tid = threadIdx.x;
    const int w = tid >> 5, lane = tid & 31;
    const int gid = lane >> 2, tig = lane & 3;
    const int nt = blockIdx.x, b = blockIdx.y;
    const int n0 = nt * CBN;
    const int wm = (w >> 1) * 32;            // 0,32,64,96
    const int wn = (w & 1) * 32;             // 0,32

    const __nv_bfloat16* eH = g_eH + (size_t)b * TD * TE;
    const __nv_bfloat16* eL = g_eL + (size_t)b * TD * TE;
    const __nv_bfloat16* Th = g_Th + (size_t)b * HE * TE;
    const __nv_bfloat16* Tl = g_Tl + (size_t)b * HE * TE;

    const int s_row0 = tid >> 2, s_q = tid & 3;
    const uint32_t s_so0 = (uint32_t)(s_row0 * 80 + s_q * 16);

    float acc[2][4][4] = {};

    auto stage = [&](int c, int s) {
        uint32_t base = sb + s * CSTAGE;
        #pragma unroll
        for (int t = 0; t < 2; t++) {
            uint32_t so = s_so0 + t * 64 * 80;
            size_t ga = (size_t)(s_row0 + 64 * t) * TE + c * 32 + s_q * 8;
            cp16(base + COFF_AH + so, eH + ga);
            cp16(base + COFF_AL + so, eL + ga);
        }
        size_t gb = (size_t)(n0 + s_row0) * TE + c * 32 + s_q * 8;
        cp16(base + COFF_BH + s_so0, Th + gb);
        cp16(base + COFF_BL + s_so0, Tl + gb);
        asm volatile("cp.async.commit_group;" ::: "memory");
    };

    stage(0, 0);

    for (int c = 0; c < TE / 32; c++) {       // 8 k-chunks
        const int s = c & 1;
        if (c + 1 < TE / 32) {
            stage(c + 1, s ^ 1);
            asm volatile("cp.async.wait_group 1;" ::: "memory");
        } else {
            asm volatile("cp.async.wait_group 0;" ::: "memory");
        }
        __syncthreads();

        const char* tAh = smem + s * CSTAGE + COFF_AH;
        const char* tAl = smem + s * CSTAGE + COFF_AL;
        const char* tBh = smem + s * CSTAGE + COFF_BH;
        const char* tBl = smem + s * CSTAGE + COFF_BL;

        #pragma unroll
        for (int ks = 0; ks < 2; ks++) {
            const uint32_t kb = ks * 32 + 4 * tig;
            uint32_t aH[2][4], aL[2][4], bH[4][2], bL[4][2];
            #pragma unroll
            for (int mi = 0; mi < 2; mi++) {
                uint32_t ra = (uint32_t)((wm + mi * 16 + gid) * 80) + kb;
                aH[mi][0] = *(const uint32_t*)(tAh + ra);
                aH[mi][1] = *(const uint32_t*)(tAh + ra + 8 * 80);
                aH[mi][2] = *(const uint32_t*)(tAh + ra + 16);
                aH[mi][3] = *(const uint32_t*)(tAh + ra + 8 * 80 + 16);
                aL[mi][0] = *(const uint32_t*)(tAl + ra);
                aL[mi][1] = *(const uint32_t*)(tAl + ra + 8 * 80);
                aL[mi][2] = *(const uint32_t*)(tAl + ra + 16);
                aL[mi][3] = *(const uint32_t*)(tAl + ra + 8 * 80 + 16);
            }
            #pragma unroll
            for (int ni = 0; ni < 4; ni++) {
                uint32_t rb = (uint32_t)((wn + ni * 8 + gid) * 80) + kb;
                bH[ni][0] = *(const uint32_t*)(tBh + rb);
                bH[ni][1] = *(const uint32_t*)(tBh + rb + 16);
                bL[ni][0] = *(const uint32_t*)(tBl + rb);
                bL[ni][1] = *(const uint32_t*)(tBl + rb + 16);
            }
            #pragma unroll
            for (int mi = 0; mi < 2; mi++)
                #pragma unroll
                for (int ni = 0; ni < 4; ni++) {
                    mma_bf16(acc[mi][ni], aH[mi], bH[ni]);
                    mma_bf16(acc[mi][ni], aL[mi], bH[ni]);
                    mma_bf16(acc[mi][ni], aH[mi], bL[ni]);
                }
        }
        __syncthreads();
    }

    const int er = gid, ec = 2 * tig;
    #pragma unroll
    for (int mi = 0; mi < 2; mi++)
        #pragma unroll
        for (int ni = 0; ni < 4; ni++) {
            int row = wm + mi * 16 + er;                 // d
            int col = n0 + wn + ni * 8 + ec;             // h
            *(float2*)&outC[(size_t)(b * TD + row) * HE + col] =
                make_float2(acc[mi][ni][0], acc[mi][ni][1]);
            *(float2*)&outC[(size_t)(b * TD + row + 8) * HE + col] =
                make_float2(acc[mi][ni][2], acc[mi][ni][3]);
        }
}

// ================= launch =================
extern "C" void kernel_launch(void* const* d_in, const int* in_sizes, int n_in,
                              void* d_out, int out_size) {
    const float* enc = (const float*)d_in[0];
    const float* dec = (const float*)d_in[1];
    const float* W_a = (const float*)d_in[2];
    const float* U_a = (const float*)d_in[3];
    const float* V_a = (const float*)d_in[4];

    float* outC = (float*)d_out;
    float* outE = (float*)d_out + BATCH * TD * HE;

    cudaFuncSetAttribute(gemm_tc, cudaFuncAttributeMaxDynamicSharedMemorySize, GEMM_SMEM);
    cudaFuncSetAttribute(ctx_mma, cudaFuncAttributeMaxDynamicSharedMemorySize, CTX_SMEM);

    conv_all<<<CONV_A_BLOCKS + 512 + 1024, 512>>>(enc, dec, W_a, U_a);
    gemm_tc<<<dim3(HE / BN, MROWS / 128), 256, GEMM_SMEM>>>();
    e_comp<<<dim3(2, TD / DT, BATCH), 512>>>(V_a);
    softmax_cvt<<<dim3(TD / DT, BATCH), 256>>>(outE);
    ctx_mma<<<dim3(HE / CBN, BATCH), 256, CTX_SMEM>>>(outC);
}